// round 3
// baseline (speedup 1.0000x reference)
#include <cuda_runtime.h>

#define N_NODES 16384
#define A_ANCH  256
#define D_LAT   32

// ---------------------------------------------------------------------------
// Single fused kernel.
//   out[n,:] = (1/A) * (dists[:,n]^T @ E_anchor) @ W1 + c
//   c        = b + (1/A) * colsum(embeds[:A]) @ W2
//
// Block = 256 threads = 8 warps. Warp w owns anchors [w*32, w*32+32).
// Lane: slot = lane&7 (4 n's each), quarter = lane>>3 (8 cols of T each).
// Thread tile: T[4n x 8d] as 16 packed f32x2 accumulators.
// Block covers 32 n; grid = 512.
// dists: LDG.128, prefetch depth 8. E rows: 2x LDS.128 broadcast.
// 8 a-group partials: log2 SMEM tree. Epilogue: T @ (W1/256) + c.
// ---------------------------------------------------------------------------
__global__ __launch_bounds__(256, 2) void pnn_fused_kernel(
    const float* __restrict__ embeds,     // [N, 32]
    const float* __restrict__ dists,      // [A, N]
    const float* __restrict__ W,          // [64, 32]
    const float* __restrict__ b,          // [32]
    const int*   __restrict__ anchor_ids, // [A]
    float*       __restrict__ out)        // [N, 32]
{
    __shared__ __align__(16) unsigned long long sh[4096]; // 32 KB: E_anchor, then reduction
    __shared__ __align__(16) float Wsh[2048];             // 8 KB: W/256 (W1 rows 0-31, W2 rows 32-63)
    __shared__ float ssh2[256];                           // per-group colsum partials [8][32]
    __shared__ __align__(16) float Tsh[32 * 32];          // 4 KB: reduced T tile
    __shared__ __align__(16) float csh[32];

    float* Esh = (float*)sh;

    const int t       = threadIdx.x;
    const int lane    = t & 31;
    const int slot    = lane & 7;
    const int quarter = lane >> 3;
    const int group   = t >> 5;
    const int a0      = group * 32;
    const int n0      = blockIdx.x * 32 + slot * 4;

    // ---- issue dists prefetches FIRST (DRAM streaming starts immediately) ----
    const float* dp = dists + (size_t)a0 * N_NODES + n0;
    float4 pf[8];
    #pragma unroll
    for (int i = 0; i < 8; i++)
        pf[i] = *(const float4*)(dp + (size_t)i * N_NODES);

    // ---- prologue: W (scaled by 1/256), anchor gather, colsum partials ----
    {
        const float4* Wsrc = (const float4*)W;
        float4* Wdst = (float4*)Wsh;
        #pragma unroll
        for (int i = 0; i < 2; i++) {
            float4 w = Wsrc[t + 256 * i];
            w.x *= (1.0f / 256.0f); w.y *= (1.0f / 256.0f);
            w.z *= (1.0f / 256.0f); w.w *= (1.0f / 256.0f);
            Wdst[t + 256 * i] = w;
        }
    }
    {
        // gather anchor row t into Esh[t][:]
        int id = anchor_ids[t];
        const float4* src = (const float4*)(embeds + (size_t)id * D_LAT);
        float4* dst = (float4*)(Esh + t * D_LAT);
        #pragma unroll
        for (int i = 0; i < 8; i++) dst[i] = src[i];
    }
    {
        // colsum partials over embeds[0:256]: group g sums rows g*32..g*32+31, col j
        int j = t & 31;
        int g = t >> 5;
        float part = 0.f;
        #pragma unroll 4
        for (int i = 0; i < 32; i++)
            part += embeds[(size_t)(g * 32 + i) * D_LAT + j];
        ssh2[g * 32 + j] = part;
    }
    __syncthreads();

    // ---- main loop: T[4n x 8d] += dists * E ----
    unsigned long long acc[16];
    #pragma unroll
    for (int i = 0; i < 16; i++) acc[i] = 0ULL;

    const float* erow = Esh + a0 * D_LAT + quarter * 8;

    #pragma unroll
    for (int it = 0; it < 32; it += 8) {
        #pragma unroll
        for (int u = 0; u < 8; u++) {
            const int step = it + u;
            float4 d = pf[u];
            if (step + 8 < 32)
                pf[u] = *(const float4*)(dp + (size_t)(step + 8) * N_NODES);

            unsigned long long dd0, dd1, dd2, dd3;
            asm("mov.b64 %0,{%1,%1};" : "=l"(dd0) : "f"(d.x));
            asm("mov.b64 %0,{%1,%1};" : "=l"(dd1) : "f"(d.y));
            asm("mov.b64 %0,{%1,%1};" : "=l"(dd2) : "f"(d.z));
            asm("mov.b64 %0,{%1,%1};" : "=l"(dd3) : "f"(d.w));

            const ulonglong2* ep = (const ulonglong2*)(erow + step * D_LAT);
            ulonglong2 m0 = ep[0], m1 = ep[1];

            #define FMA4(nn, dd)                                                           \
                asm("fma.rn.f32x2 %0,%1,%2,%0;" : "+l"(acc[(nn)*4+0]) : "l"(dd), "l"(m0.x)); \
                asm("fma.rn.f32x2 %0,%1,%2,%0;" : "+l"(acc[(nn)*4+1]) : "l"(dd), "l"(m0.y)); \
                asm("fma.rn.f32x2 %0,%1,%2,%0;" : "+l"(acc[(nn)*4+2]) : "l"(dd), "l"(m1.x)); \
                asm("fma.rn.f32x2 %0,%1,%2,%0;" : "+l"(acc[(nn)*4+3]) : "l"(dd), "l"(m1.y));
            FMA4(0, dd0)
            FMA4(1, dd1)
            FMA4(2, dd2)
            FMA4(3, dd3)
            #undef FMA4
        }
    }

    // ---- log2 tree reduction over the 8 a-groups (reuse sh) ----
    __syncthreads();
    #pragma unroll
    for (int s = 128; s >= 32; s >>= 1) {
        if (t >= s && t < 2 * s) {
            #pragma unroll
            for (int i = 0; i < 16; i++) sh[i * s + (t - s)] = acc[i];
        }
        __syncthreads();
        if (t < s) {
            #pragma unroll
            for (int i = 0; i < 16; i++)
                asm("add.rn.f32x2 %0,%0,%1;" : "+l"(acc[i]) : "l"(sh[i * s + t]));
        }
        __syncthreads();
    }

    // ---- threads 0..31: write T tile to Tsh; warp 0 also computes c ----
    if (t < 32) {
        unsigned long long* T64 = (unsigned long long*)Tsh;
        #pragma unroll
        for (int nn = 0; nn < 4; nn++) {
            int base = ((slot * 4 + nn) * D_LAT + quarter * 8) >> 1;
            #pragma unroll
            for (int k = 0; k < 4; k++) T64[base + k] = acc[nn * 4 + k];
        }
        // c[j] = b[j] + sum_d colsum[d] * (W2[d][j]/256)
        float accc = b[t];
        #pragma unroll
        for (int d = 0; d < D_LAT; d++) {
            float s_d = ssh2[d] + ssh2[32 + d] + ssh2[64 + d] + ssh2[96 + d]
                      + ssh2[128 + d] + ssh2[160 + d] + ssh2[192 + d] + ssh2[224 + d];
            accc += s_d * Wsh[(D_LAT + d) * D_LAT + t];
        }
        csh[t] = accc;
    }
    __syncthreads();

    // ---- epilogue: out[n,:] = T[n,:] @ (W1/256) + c ----
    {
        const int n  = t >> 3;       // 0..31
        const int j4 = (t & 7) * 4;  // output col group
        float4 o = make_float4(0.f, 0.f, 0.f, 0.f);
        const float* Trow = Tsh + n * D_LAT;
        #pragma unroll
        for (int d = 0; d < D_LAT; d++) {
            float tv = Trow[d];
            float4 w = *(const float4*)(Wsh + d * D_LAT + j4);
            o.x += tv * w.x; o.y += tv * w.y; o.z += tv * w.z; o.w += tv * w.w;
        }
        float4 c = *(const float4*)(csh + j4);
        o.x += c.x; o.y += c.y; o.z += c.z; o.w += c.w;
        *(float4*)(out + (size_t)(blockIdx.x * 32 + n) * D_LAT + j4) = o;
    }
}

extern "C" void kernel_launch(void* const* d_in, const int* in_sizes, int n_in,
                              void* d_out, int out_size)
{
    const float* embeds     = (const float*)d_in[0];
    const float* dists      = (const float*)d_in[1];
    const float* W_hidden   = (const float*)d_in[2];
    const float* b_hidden   = (const float*)d_in[3];
    const int*   anchor_ids = (const int*)  d_in[4];
    float*       out        = (float*)d_out;

    pnn_fused_kernel<<<N_NODES / 32, 256>>>(embeds, dists, W_hidden, b_hidden,
                                            anchor_ids, out);
}

// round 4
// speedup vs baseline: 1.6875x; 1.6875x over previous
#include <cuda_runtime.h>

#define N_NODES 16384
#define A_ANCH  256
#define D_LAT   32

// Precomputed (1/A) * (anchor_emb @ W1)  and  c[j] = b[j] + (1/A)*sum_a (embeds[a] @ W2)[j]
__device__ float g_M[A_ANCH * D_LAT];   // 32 KB
__device__ float g_c[D_LAT];

// ---------------------------------------------------------------------------
// Kernel 1: precompute g_M and g_c. Grid = 9 blocks x 256 threads.
// ---------------------------------------------------------------------------
__global__ __launch_bounds__(256) void precompute_kernel(
    const float* __restrict__ embeds,
    const float* __restrict__ W,       // [64,32] row-major: W1 = rows 0..31, W2 = rows 32..63
    const float* __restrict__ b,       // [32]
    const int*   __restrict__ anchor_ids)
{
    __shared__ float Wsh[D_LAT * D_LAT];
    __shared__ float esh[32][32];
    __shared__ float ssh[D_LAT];

    const int t   = threadIdx.x;
    const int blk = blockIdx.x;
    const int j   = t & 31;

    if (blk < 8) {
        #pragma unroll
        for (int i = t; i < D_LAT * D_LAT; i += 256) Wsh[i] = W[i];
        for (int r = t >> 5; r < 32; r += 8) {
            int id = anchor_ids[blk * 32 + r];
            esh[r][j] = embeds[id * D_LAT + j];
        }
        __syncthreads();
        for (int r = t >> 5; r < 32; r += 8) {
            float acc = 0.f;
            #pragma unroll
            for (int d = 0; d < D_LAT; d++) acc += esh[r][d] * Wsh[d * D_LAT + j];
            g_M[(blk * 32 + r) * D_LAT + j] = acc * (1.0f / 256.0f);
        }
    } else {
        #pragma unroll
        for (int i = t; i < D_LAT * D_LAT; i += 256) Wsh[i] = W[D_LAT * D_LAT + i];
        if (t < D_LAT) ssh[t] = 0.f;
        __syncthreads();
        {
            int grp = t >> 5;
            float part = 0.f;
            #pragma unroll 4
            for (int i = 0; i < 32; i++)
                part += embeds[(grp * 32 + i) * D_LAT + j];
            atomicAdd(&ssh[j], part);
        }
        __syncthreads();
        if (t < D_LAT) {
            float acc = 0.f;
            #pragma unroll
            for (int d = 0; d < D_LAT; d++) acc += ssh[d] * Wsh[d * D_LAT + t];
            g_c[t] = b[t] + acc * (1.0f / 256.0f);
        }
    }
}

// ---------------------------------------------------------------------------
// Kernel 2: out[n,:] = sum_a dists[a,n] * g_M[a,:]  +  g_c
//
// Block = 256 threads = 8 slots (4n each) x 4 quarters (8d each) x 8 a-groups.
// Thread tile: 4n x 8d = 16 packed f32x2 accumulators (~70 regs total).
// 3 blocks/SM (launch_bounds 256,3); grid 512 x 32n.
// PDL: dists prefetches issue before cudaGridDependencySynchronize();
//      g_M is only read after it.
// ---------------------------------------------------------------------------
__global__ __launch_bounds__(256, 3) void pnn_main_kernel(
    const float* __restrict__ dists,   // [A, N]
    float*       __restrict__ out)     // [N, D]
{
    __shared__ __align__(16) unsigned long long sh[4096];   // 32 KB: M, then reduction
    float* Msh = (float*)sh;

    const int t       = threadIdx.x;
    const int slot    = t & 7;
    const int quarter = (t >> 3) & 3;
    const int group   = t >> 5;
    const int n0      = blockIdx.x * 32 + slot * 4;
    const int a0      = group * 32;

    // ---- dists prefetches first: independent of the precompute kernel ----
    const float* dp = dists + (size_t)a0 * N_NODES + n0;
    float4 pf[4];
    #pragma unroll
    for (int i = 0; i < 4; i++)
        pf[i] = *(const float4*)(dp + (size_t)i * N_NODES);

    // ---- wait for precompute kernel results (PDL) ----
    cudaGridDependencySynchronize();

    // ---- load M (32 KB) into shared ----
    {
        const float4* src = (const float4*)g_M;
        float4*       dst = (float4*)Msh;
        #pragma unroll
        for (int i = 0; i < 8; i++) dst[t + 256 * i] = src[t + 256 * i];
    }
    __syncthreads();

    unsigned long long acc[16];
    #pragma unroll
    for (int i = 0; i < 16; i++) acc[i] = 0ULL;

    const float* mrow = Msh + a0 * D_LAT + quarter * 8;

    #pragma unroll
    for (int it = 0; it < 32; it += 4) {
        #pragma unroll
        for (int u = 0; u < 4; u++) {
            const int step = it + u;
            float4 d = pf[u];
            if (step + 4 < 32)
                pf[u] = *(const float4*)(dp + (size_t)(step + 4) * N_NODES);

            unsigned long long dd0, dd1, dd2, dd3;
            asm("mov.b64 %0,{%1,%1};" : "=l"(dd0) : "f"(d.x));
            asm("mov.b64 %0,{%1,%1};" : "=l"(dd1) : "f"(d.y));
            asm("mov.b64 %0,{%1,%1};" : "=l"(dd2) : "f"(d.z));
            asm("mov.b64 %0,{%1,%1};" : "=l"(dd3) : "f"(d.w));

            const ulonglong2* mp = (const ulonglong2*)(mrow + step * D_LAT);
            ulonglong2 m0 = mp[0], m1 = mp[1];

            #define FMA4(nn, dd)                                                           \
                asm("fma.rn.f32x2 %0,%1,%2,%0;" : "+l"(acc[(nn)*4+0]) : "l"(dd), "l"(m0.x)); \
                asm("fma.rn.f32x2 %0,%1,%2,%0;" : "+l"(acc[(nn)*4+1]) : "l"(dd), "l"(m0.y)); \
                asm("fma.rn.f32x2 %0,%1,%2,%0;" : "+l"(acc[(nn)*4+2]) : "l"(dd), "l"(m1.x)); \
                asm("fma.rn.f32x2 %0,%1,%2,%0;" : "+l"(acc[(nn)*4+3]) : "l"(dd), "l"(m1.y));
            FMA4(0, dd0)
            FMA4(1, dd1)
            FMA4(2, dd2)
            FMA4(3, dd3)
            #undef FMA4
        }
    }

    // ---- log2 tree reduction over the 8 a-groups (reuse sh) ----
    __syncthreads();
    #pragma unroll
    for (int s = 128; s >= 32; s >>= 1) {
        if (t >= s && t < 2 * s) {
            #pragma unroll
            for (int i = 0; i < 16; i++) sh[i * s + (t - s)] = acc[i];
        }
        __syncthreads();
        if (t < s) {
            #pragma unroll
            for (int i = 0; i < 16; i++)
                asm("add.rn.f32x2 %0,%0,%1;" : "+l"(acc[i]) : "l"(sh[i * s + t]));
        }
        __syncthreads();
    }

    // ---- epilogue: threads 0..31 hold final sums for this block's 32 n ----
    if (t < 32) {
        const unsigned long long* c64 = (const unsigned long long*)g_c;
        unsigned long long cc[4];
        #pragma unroll
        for (int k = 0; k < 4; k++) cc[k] = c64[quarter * 4 + k];
        #pragma unroll
        for (int i = 0; i < 16; i++)
            asm("add.rn.f32x2 %0,%0,%1;" : "+l"(acc[i]) : "l"(cc[i & 3]));

        #pragma unroll
        for (int n = 0; n < 4; n++) {
            float* orow = out + (size_t)(n0 + n) * D_LAT + quarter * 8;
            ulonglong2 v0, v1;
            v0.x = acc[n * 4 + 0]; v0.y = acc[n * 4 + 1];
            v1.x = acc[n * 4 + 2]; v1.y = acc[n * 4 + 3];
            *(ulonglong2*)(orow)     = v0;
            *(ulonglong2*)(orow + 4) = v1;
        }
    }
}

extern "C" void kernel_launch(void* const* d_in, const int* in_sizes, int n_in,
                              void* d_out, int out_size)
{
    const float* embeds     = (const float*)d_in[0];
    const float* dists      = (const float*)d_in[1];
    const float* W_hidden   = (const float*)d_in[2];
    const float* b_hidden   = (const float*)d_in[3];
    const int*   anchor_ids = (const int*)  d_in[4];
    float*       out        = (float*)d_out;

    precompute_kernel<<<9, 256>>>(embeds, W_hidden, b_hidden, anchor_ids);

    // Main kernel with programmatic dependent launch (overlaps with kernel 1).
    cudaLaunchConfig_t cfg = {};
    cfg.gridDim  = dim3(N_NODES / 32, 1, 1);
    cfg.blockDim = dim3(256, 1, 1);
    cfg.dynamicSmemBytes = 0;
    cfg.stream = 0;
    cudaLaunchAttribute attr[1];
    attr[0].id = cudaLaunchAttributeProgrammaticStreamSerialization;
    attr[0].val.programmaticStreamSerializationAllowed = 1;
    cfg.attrs = attr;
    cfg.numAttrs = 1;

    cudaError_t e = cudaLaunchKernelEx(&cfg, pnn_main_kernel, dists, out);
    if (e != cudaSuccess) {
        // Fallback: plain dependent launch (still correct, just serialized).
        pnn_main_kernel<<<N_NODES / 32, 256>>>(dists, out);
    }
}